// round 9
// baseline (speedup 1.0000x reference)
#include <cuda_runtime.h>
#include <cuda_bf16.h>

// 2x FIR upsample (upfirdn2d), separable [1,3,3,1]/4 tap, depthwise, fp32.
// Input (B*C, 128, 128) -> Output (B*C, 256, 256).
//
//   out[2y  ] = (1*x[y-1] + 3*x[y  ]) / 4   vertically, same horizontally
//   out[2y+1] = (3*x[y  ] + 1*x[y+1]) / 4
//
// Thread tx in [0,64) covers out cols 4tx..4tx+3 (input cols 2tx-1..2tx+2).
// Each thread computes 4 output rows (4t..4t+3) for TWO planes (p0 = 2*bz,
// p1 = 2*bz+1), with all 8 row loads front-batched for MLP=8.
// Halos come from neighbor lanes via warp shuffle; warp-edge lanes use
// predicated scalar loads. Warp stores are 512B contiguous streaming (.cs).

#define H_IN  128
#define W_IN  128
#define W_OUT 256

__device__ __forceinline__ void stcs4(float* p, float4 v) {
    asm volatile("st.global.cs.v4.f32 [%0], {%1,%2,%3,%4};"
                 :: "l"(p), "f"(v.x), "f"(v.y), "f"(v.z), "f"(v.w) : "memory");
}

__global__ __launch_bounds__(256) void upfir2x_kernel(
    const float* __restrict__ in, float* __restrict__ out)
{
    const int p0 = 2 * blockIdx.z;                         // first of two planes
    const int tx = threadIdx.x;                            // 0..63 -> out cols 4tx..4tx+3
    const int t  = blockIdx.y * blockDim.y + threadIdx.y;  // 0..63 -> out rows 4t..4t+3
    const int lane = tx & 31;                              // warps contiguous in tx

    const int xc = 2 * tx;          // input col base; need cols xc-1 .. xc+2
    const int row0 = 2 * t - 1;     // input rows row0 .. row0+3

    // ---- Phase 1: issue all 8 loads (2 planes x 4 rows), front-batched ----
    float2 v[2][4];
    float pe[2][4], ne[2][4];
    #pragma unroll
    for (int q = 0; q < 2; q++) {
        const float* src = in + (size_t)(p0 + q) * (H_IN * W_IN);
        #pragma unroll
        for (int j = 0; j < 4; j++) {
            const int row = row0 + j;
            v[q][j] = make_float2(0.f, 0.f);
            pe[q][j] = 0.f; ne[q][j] = 0.f;
            if (row >= 0 && row < H_IN) {          // warp-uniform predicate
                const float* r = src + row * W_IN;
                v[q][j] = *reinterpret_cast<const float2*>(r + xc);  // coalesced
                if (lane == 0  && xc > 0)        pe[q][j] = __ldg(r + xc - 1);
                if (lane == 31 && xc + 2 < W_IN) ne[q][j] = __ldg(r + xc + 2);
            }
        }
    }

    // ---- Phase 2+3 per plane: shuffles, horizontal taps, vertical combine ----
    const float s = 1.0f / 16.0f;
    #pragma unroll
    for (int q = 0; q < 2; q++) {
        float h[4][4];
        #pragma unroll
        for (int j = 0; j < 4; j++) {
            float p = __shfl_up_sync(0xffffffffu, v[q][j].y, 1);
            float n = __shfl_down_sync(0xffffffffu, v[q][j].x, 1);
            if (lane == 0)  p = pe[q][j];
            if (lane == 31) n = ne[q][j];

            h[j][0] = fmaf(3.f, v[q][j].x, p);          // 1*in[2tx-1] + 3*in[2tx]
            h[j][1] = fmaf(3.f, v[q][j].x, v[q][j].y);  // 3*in[2tx]   + 1*in[2tx+1]
            h[j][2] = fmaf(3.f, v[q][j].y, v[q][j].x);  // 1*in[2tx]   + 3*in[2tx+1]
            h[j][3] = fmaf(3.f, v[q][j].y, n);          // 3*in[2tx+1] + 1*in[2tx+2]
        }

        // out rows: 4t = 1*h[0]+3*h[1]; 4t+1 = 3*h[1]+1*h[2];
        //           4t+2 = 1*h[1]+3*h[2]; 4t+3 = 3*h[2]+1*h[3]
        float* dst = out + (size_t)(p0 + q) * (W_OUT * W_OUT)
                         + (size_t)(4 * t) * W_OUT + tx * 4;
        {
            float4 o;
            o.x = fmaf(3.f, h[1][0], h[0][0]) * s;
            o.y = fmaf(3.f, h[1][1], h[0][1]) * s;
            o.z = fmaf(3.f, h[1][2], h[0][2]) * s;
            o.w = fmaf(3.f, h[1][3], h[0][3]) * s;
            stcs4(dst, o);
        }
        {
            float4 o;
            o.x = fmaf(3.f, h[1][0], h[2][0]) * s;
            o.y = fmaf(3.f, h[1][1], h[2][1]) * s;
            o.z = fmaf(3.f, h[1][2], h[2][2]) * s;
            o.w = fmaf(3.f, h[1][3], h[2][3]) * s;
            stcs4(dst + W_OUT, o);
        }
        {
            float4 o;
            o.x = fmaf(3.f, h[2][0], h[1][0]) * s;
            o.y = fmaf(3.f, h[2][1], h[1][1]) * s;
            o.z = fmaf(3.f, h[2][2], h[1][2]) * s;
            o.w = fmaf(3.f, h[2][3], h[1][3]) * s;
            stcs4(dst + 2 * W_OUT, o);
        }
        {
            float4 o;
            o.x = fmaf(3.f, h[2][0], h[3][0]) * s;
            o.y = fmaf(3.f, h[2][1], h[3][1]) * s;
            o.z = fmaf(3.f, h[2][2], h[3][2]) * s;
            o.w = fmaf(3.f, h[2][3], h[3][3]) * s;
            stcs4(dst + 3 * W_OUT, o);
        }
    }
}

extern "C" void kernel_launch(void* const* d_in, const int* in_sizes, int n_in,
                              void* d_out, int out_size) {
    const float* x = (const float*)d_in[0];
    float* out = (float*)d_out;

    const int planes = in_sizes[0] / (H_IN * W_IN);   // B*C = 1024

    dim3 block(64, 4, 1);              // 256 threads: 64 col-quads x 4 row-groups
    dim3 grid(1, 64 / 4, planes / 2);  // 16 row-group blocks x 512 plane-pairs
    upfir2x_kernel<<<grid, block>>>(x, out);
}

// round 10
// speedup vs baseline: 1.0243x; 1.0243x over previous
#include <cuda_runtime.h>
#include <cuda_bf16.h>

// 2x FIR upsample (upfirdn2d), separable [1,3,3,1]/4 tap, depthwise, fp32.
// Input (B*C, 128, 128) -> Output (B*C, 256, 256).
//
//   out[2y  ] = (1*x[y-1] + 3*x[y  ]) / 4   vertically, same horizontally
//   out[2y+1] = (3*x[y  ] + 1*x[y+1]) / 4
//
// Thread tx in [0,64) covers out cols 4tx..4tx+3 (input cols 2tx-1..2tx+2).
// Each thread computes 4 output rows (4t..4t+3) from input rows 2t-1..2t+2.
// All 4 row loads are issued before any dependent math (front-batched MLP).
// Halos come from neighbor lanes via warp shuffle; warp-edge lanes use
// predicated scalar loads. Warp stores are 512B contiguous streaming (.cs).
//
// This config (256-thread 64x4 blocks, 32 regs, occ ~83%) is the measured
// optimum: the kernel is pinned at the HBM write-stream ceiling (~5.5 TB/s,
// DRAM traffic == output stream only; input is L2-resident). Larger tiles
// (8 rows, 2 planes, 512-thread blocks) all reduce occupancy or locality and
// measured slower.

#define H_IN  128
#define W_IN  128
#define W_OUT 256

__device__ __forceinline__ void stcs4(float* p, float4 v) {
    asm volatile("st.global.cs.v4.f32 [%0], {%1,%2,%3,%4};"
                 :: "l"(p), "f"(v.x), "f"(v.y), "f"(v.z), "f"(v.w) : "memory");
}

__global__ __launch_bounds__(256) void upfir2x_kernel(
    const float* __restrict__ in, float* __restrict__ out)
{
    const int plane = blockIdx.z;
    const int tx = threadIdx.x;                            // 0..63 -> out cols 4tx..4tx+3
    const int t  = blockIdx.y * blockDim.y + threadIdx.y;  // 0..63 -> out rows 4t..4t+3
    const int lane = tx & 31;                              // warps contiguous in tx

    const float* src = in + (size_t)plane * (H_IN * W_IN);
    const int xc = 2 * tx;          // input col base; need cols xc-1 .. xc+2
    const int row0 = 2 * t - 1;     // input rows row0 .. row0+3

    // ---- Phase 1: issue all loads (front-batched, MLP=4) ----
    float2 v[4];
    float pe[4], ne[4];
    #pragma unroll
    for (int j = 0; j < 4; j++) {
        const int row = row0 + j;
        v[j] = make_float2(0.f, 0.f);
        pe[j] = 0.f; ne[j] = 0.f;
        if (row >= 0 && row < H_IN) {          // warp-uniform predicate
            const float* r = src + row * W_IN;
            v[j] = *reinterpret_cast<const float2*>(r + xc);   // coalesced 256B/warp
            if (lane == 0  && xc > 0)        pe[j] = __ldg(r + xc - 1);
            if (lane == 31 && xc + 2 < W_IN) ne[j] = __ldg(r + xc + 2);
        }
    }

    // ---- Phase 2: shuffles + horizontal taps (unnormalized) ----
    float h[4][4];
    #pragma unroll
    for (int j = 0; j < 4; j++) {
        float p = __shfl_up_sync(0xffffffffu, v[j].y, 1);
        float n = __shfl_down_sync(0xffffffffu, v[j].x, 1);
        if (lane == 0)  p = pe[j];
        if (lane == 31) n = ne[j];

        h[j][0] = fmaf(3.f, v[j].x, p);        // out col 4tx   : in[2tx-1] + 3*in[2tx]
        h[j][1] = fmaf(3.f, v[j].x, v[j].y);   // out col 4tx+1 : 3*in[2tx] + in[2tx+1]
        h[j][2] = fmaf(3.f, v[j].y, v[j].x);   // out col 4tx+2 : in[2tx] + 3*in[2tx+1]
        h[j][3] = fmaf(3.f, v[j].y, n);        // out col 4tx+3 : 3*in[2tx+1] + in[2tx+2]
    }

    // ---- Phase 3: vertical combine (/16 at end) ----
    //   4t   = 1*h[0] + 3*h[1]
    //   4t+1 = 3*h[1] + 1*h[2]
    //   4t+2 = 1*h[1] + 3*h[2]
    //   4t+3 = 3*h[2] + 1*h[3]
    const float s = 1.0f / 16.0f;
    float* dst = out + (size_t)plane * (W_OUT * W_OUT)
                     + (size_t)(4 * t) * W_OUT + tx * 4;

    {
        float4 o;
        o.x = fmaf(3.f, h[1][0], h[0][0]) * s;
        o.y = fmaf(3.f, h[1][1], h[0][1]) * s;
        o.z = fmaf(3.f, h[1][2], h[0][2]) * s;
        o.w = fmaf(3.f, h[1][3], h[0][3]) * s;
        stcs4(dst, o);
    }
    {
        float4 o;
        o.x = fmaf(3.f, h[1][0], h[2][0]) * s;
        o.y = fmaf(3.f, h[1][1], h[2][1]) * s;
        o.z = fmaf(3.f, h[1][2], h[2][2]) * s;
        o.w = fmaf(3.f, h[1][3], h[2][3]) * s;
        stcs4(dst + W_OUT, o);
    }
    {
        float4 o;
        o.x = fmaf(3.f, h[2][0], h[1][0]) * s;
        o.y = fmaf(3.f, h[2][1], h[1][1]) * s;
        o.z = fmaf(3.f, h[2][2], h[1][2]) * s;
        o.w = fmaf(3.f, h[2][3], h[1][3]) * s;
        stcs4(dst + 2 * W_OUT, o);
    }
    {
        float4 o;
        o.x = fmaf(3.f, h[2][0], h[3][0]) * s;
        o.y = fmaf(3.f, h[2][1], h[3][1]) * s;
        o.z = fmaf(3.f, h[2][2], h[3][2]) * s;
        o.w = fmaf(3.f, h[2][3], h[3][3]) * s;
        stcs4(dst + 3 * W_OUT, o);
    }
}

extern "C" void kernel_launch(void* const* d_in, const int* in_sizes, int n_in,
                              void* d_out, int out_size) {
    const float* x = (const float*)d_in[0];
    float* out = (float*)d_out;

    const int planes = in_sizes[0] / (H_IN * W_IN);   // B*C = 1024

    dim3 block(64, 4, 1);            // 256 threads: 64 col-quads x 4 row-groups
    dim3 grid(1, 64 / 4, planes);    // 16 row-group blocks x 1024 planes
    upfir2x_kernel<<<grid, block>>>(x, out);
}

// round 11
// speedup vs baseline: 1.0249x; 1.0006x over previous
#include <cuda_runtime.h>
#include <cuda_bf16.h>

// 2x FIR upsample (upfirdn2d), separable [1,3,3,1]/4 tap, depthwise, fp32.
// Input (B*C, 128, 128) -> Output (B*C, 256, 256).
//
//   out[2y  ] = (1*x[y-1] + 3*x[y  ]) / 4   vertically, same horizontally
//   out[2y+1] = (3*x[y  ] + 1*x[y+1]) / 4
//
// Thread tx in [0,64) covers out cols 4tx..4tx+3 (input cols 2tx-1..2tx+2).
// Each thread computes 4 output rows (4t..4t+3) from input rows 2t-1..2t+2.
// All 4 row loads are issued before any dependent math (front-batched MLP).
// Halos come from neighbor lanes via warp shuffle; warp-edge lanes use
// predicated scalar loads. Warp stores are 512B contiguous streaming (.cs).
//
// CONVERGED OPTIMUM (R10): 256-thread 64x4 blocks, 32 regs, occ ~82%.
// DRAM traffic == output stream only (~276 MB; input L2-resident), sustained
// 5.5 TB/s = ~69% of spec — the achievable HBM write-stream ceiling. Variants
// with more work per thread (8 rows, 2 planes, 512-thread blocks) all traded
// away occupancy and measured slower.

#define H_IN  128
#define W_IN  128
#define W_OUT 256

__device__ __forceinline__ void stcs4(float* p, float4 v) {
    asm volatile("st.global.cs.v4.f32 [%0], {%1,%2,%3,%4};"
                 :: "l"(p), "f"(v.x), "f"(v.y), "f"(v.z), "f"(v.w) : "memory");
}

__global__ __launch_bounds__(256) void upfir2x_kernel(
    const float* __restrict__ in, float* __restrict__ out)
{
    const int plane = blockIdx.z;
    const int tx = threadIdx.x;                            // 0..63 -> out cols 4tx..4tx+3
    const int t  = blockIdx.y * blockDim.y + threadIdx.y;  // 0..63 -> out rows 4t..4t+3
    const int lane = tx & 31;                              // warps contiguous in tx

    const float* src = in + (size_t)plane * (H_IN * W_IN);
    const int xc = 2 * tx;          // input col base; need cols xc-1 .. xc+2
    const int row0 = 2 * t - 1;     // input rows row0 .. row0+3

    // ---- Phase 1: issue all loads (front-batched, MLP=4) ----
    float2 v[4];
    float pe[4], ne[4];
    #pragma unroll
    for (int j = 0; j < 4; j++) {
        const int row = row0 + j;
        v[j] = make_float2(0.f, 0.f);
        pe[j] = 0.f; ne[j] = 0.f;
        if (row >= 0 && row < H_IN) {          // warp-uniform predicate
            const float* r = src + row * W_IN;
            v[j] = *reinterpret_cast<const float2*>(r + xc);   // coalesced 256B/warp
            if (lane == 0  && xc > 0)        pe[j] = __ldg(r + xc - 1);
            if (lane == 31 && xc + 2 < W_IN) ne[j] = __ldg(r + xc + 2);
        }
    }

    // ---- Phase 2: shuffles + horizontal taps (unnormalized) ----
    float h[4][4];
    #pragma unroll
    for (int j = 0; j < 4; j++) {
        float p = __shfl_up_sync(0xffffffffu, v[j].y, 1);
        float n = __shfl_down_sync(0xffffffffu, v[j].x, 1);
        if (lane == 0)  p = pe[j];
        if (lane == 31) n = ne[j];

        h[j][0] = fmaf(3.f, v[j].x, p);        // out col 4tx   : in[2tx-1] + 3*in[2tx]
        h[j][1] = fmaf(3.f, v[j].x, v[j].y);   // out col 4tx+1 : 3*in[2tx] + in[2tx+1]
        h[j][2] = fmaf(3.f, v[j].y, v[j].x);   // out col 4tx+2 : in[2tx] + 3*in[2tx+1]
        h[j][3] = fmaf(3.f, v[j].y, n);        // out col 4tx+3 : 3*in[2tx+1] + in[2tx+2]
    }

    // ---- Phase 3: vertical combine (/16 at end) ----
    //   4t   = 1*h[0] + 3*h[1]
    //   4t+1 = 3*h[1] + 1*h[2]
    //   4t+2 = 1*h[1] + 3*h[2]
    //   4t+3 = 3*h[2] + 1*h[3]
    const float s = 1.0f / 16.0f;
    float* dst = out + (size_t)plane * (W_OUT * W_OUT)
                     + (size_t)(4 * t) * W_OUT + tx * 4;

    {
        float4 o;
        o.x = fmaf(3.f, h[1][0], h[0][0]) * s;
        o.y = fmaf(3.f, h[1][1], h[0][1]) * s;
        o.z = fmaf(3.f, h[1][2], h[0][2]) * s;
        o.w = fmaf(3.f, h[1][3], h[0][3]) * s;
        stcs4(dst, o);
    }
    {
        float4 o;
        o.x = fmaf(3.f, h[1][0], h[2][0]) * s;
        o.y = fmaf(3.f, h[1][1], h[2][1]) * s;
        o.z = fmaf(3.f, h[1][2], h[2][2]) * s;
        o.w = fmaf(3.f, h[1][3], h[2][3]) * s;
        stcs4(dst + W_OUT, o);
    }
    {
        float4 o;
        o.x = fmaf(3.f, h[2][0], h[1][0]) * s;
        o.y = fmaf(3.f, h[2][1], h[1][1]) * s;
        o.z = fmaf(3.f, h[2][2], h[1][2]) * s;
        o.w = fmaf(3.f, h[2][3], h[1][3]) * s;
        stcs4(dst + 2 * W_OUT, o);
    }
    {
        float4 o;
        o.x = fmaf(3.f, h[2][0], h[3][0]) * s;
        o.y = fmaf(3.f, h[2][1], h[3][1]) * s;
        o.z = fmaf(3.f, h[2][2], h[3][2]) * s;
        o.w = fmaf(3.f, h[2][3], h[3][3]) * s;
        stcs4(dst + 3 * W_OUT, o);
    }
}

extern "C" void kernel_launch(void* const* d_in, const int* in_sizes, int n_in,
                              void* d_out, int out_size) {
    const float* x = (const float*)d_in[0];
    float* out = (float*)d_out;

    const int planes = in_sizes[0] / (H_IN * W_IN);   // B*C = 1024

    dim3 block(64, 4, 1);            // 256 threads: 64 col-quads x 4 row-groups
    dim3 grid(1, 64 / 4, planes);    // 16 row-group blocks x 1024 planes
    upfir2x_kernel<<<grid, block>>>(x, out);
}